// round 7
// baseline (speedup 1.0000x reference)
#include <cuda_runtime.h>
#include <cuda_bf16.h>
#include <stdint.h>

#define B_   32
#define T_   4096
#define C_   1024
#define D_   64
#define TA_  2048
#define TB_  2048
#define R_   1024
#define TUN_ 1024
#define TOUT_ 3072

#define NEG_INF __int_as_float(0xff800000)
// |bf16-screened - exact| <= 2^-8 * sum|a_k b_k| + accum <= 0.004 (unit rows). Need 2x.
#define MARGIN2 0.008f
#define CAND_CAP 4096

// ---------------- scratch (static device globals; no runtime alloc) ----------------
__device__ float g_m[(size_t)B_ * T_ * D_];            // normalized metric fp32
__device__ __nv_bfloat16 g_abf[(size_t)B_ * TA_ * D_]; // bf16(normalized) even rows
__device__ __nv_bfloat16 g_bbf[(size_t)B_ * TB_ * D_]; // bf16(normalized) odd rows
__device__ float g_nmax[B_ * TA_];
__device__ int   g_nidx[B_ * TA_];
__device__ int   g_unm [B_ * TUN_];
__device__ int   g_off [B_ * (TB_ + 1)];
__device__ int   g_csr [B_ * R_];

__device__ __forceinline__ uint32_t smem_u32(const void* p) {
    uint32_t a;
    asm("{ .reg .u64 t; cvta.to.shared.u64 t, %1; cvt.u32.u64 %0, t; }" : "=r"(a) : "l"(p));
    return a;
}
__device__ __forceinline__ uint32_t swz(uint32_t x) { return x ^ (((x >> 7) & 7u) << 4); }

__device__ __forceinline__ void cp16(uint32_t dst, const void* src) {
    asm volatile("cp.async.cg.shared.global [%0], [%1], 16;" :: "r"(dst), "l"(src) : "memory");
}
__device__ __forceinline__ void cp_commit() {
    asm volatile("cp.async.commit_group;" ::: "memory");
}
template <int N>
__device__ __forceinline__ void cp_wait() {
    asm volatile("cp.async.wait_group %0;" :: "n"(N) : "memory");
}

__device__ __forceinline__ void ldsm4(uint32_t& r0, uint32_t& r1, uint32_t& r2, uint32_t& r3,
                                      uint32_t addr) {
    asm volatile("ldmatrix.sync.aligned.m8n8.x4.shared.b16 {%0,%1,%2,%3}, [%4];"
                 : "=r"(r0), "=r"(r1), "=r"(r2), "=r"(r3) : "r"(addr));
}
__device__ __forceinline__ void mma16816(float* d, uint32_t a0, uint32_t a1, uint32_t a2,
                                         uint32_t a3, uint32_t b0, uint32_t b1) {
    asm volatile(
        "mma.sync.aligned.m16n8k16.row.col.f32.bf16.bf16.f32 "
        "{%0,%1,%2,%3}, {%4,%5,%6,%7}, {%8,%9}, {%0,%1,%2,%3};"
        : "+f"(d[0]), "+f"(d[1]), "+f"(d[2]), "+f"(d[3])
        : "r"(a0), "r"(a1), "r"(a2), "r"(a3), "r"(b0), "r"(b1));
}

// ---------------- K1: normalize + fp32 copy + bf16 copies (even/odd split) ----------------
__global__ __launch_bounds__(256) void k_normalize(const float* __restrict__ metric) {
    int row  = (blockIdx.x * blockDim.x + threadIdx.x) >> 5;
    int lane = threadIdx.x & 31;
    if (row >= B_ * T_) return;
    float2 v = *(const float2*)(metric + (size_t)row * D_ + 2 * lane);
    float s = v.x * v.x + v.y * v.y;
#pragma unroll
    for (int o = 16; o > 0; o >>= 1) s += __shfl_xor_sync(0xffffffffu, s, o);
    float nrm = __fsqrt_rn(s);
    float x0 = __fdiv_rn(v.x, nrm);
    float x1 = __fdiv_rn(v.y, nrm);
    *(float2*)(g_m + (size_t)row * D_ + 2 * lane) = make_float2(x0, x1);
    int b = row >> 12;
    int t = row & (T_ - 1);
    __nv_bfloat16* arr = (t & 1) ? g_bbf : g_abf;
    size_t off = ((size_t)b * (T_ / 2) + (t >> 1)) * D_ + 2 * lane;
    *(__nv_bfloat162*)(arr + off) =
        __halves2bfloat162(__float2bfloat16_rn(x0), __float2bfloat16_rn(x1));
}

// ---------------- K2: single-pass bf16 HMMA screen + exact fp32 rescore ----------------
// Warp tile 32i x 64j: 4 i-warps x 2 j-warps. Halves B ldmatrix traffic vs 16x128.
#define SM_A    0
#define SM_B0   16384
#define SM_B1   32768
#define SM_LIST 49152
#define SM_BEST (SM_LIST + CAND_CAP * 4)
#define SM_CNT  (SM_BEST + 128 * 8)
#define SM_TOT  (SM_CNT + 16)

__global__ __launch_bounds__(256, 2) void k_screen() {
    extern __shared__ char smem[];
    uint32_t* s_list = (uint32_t*)(smem + SM_LIST);
    unsigned long long* s_best = (unsigned long long*)(smem + SM_BEST);
    int* s_cnt = (int*)(smem + SM_CNT);

    const int b   = blockIdx.y;
    const int i0  = blockIdx.x * 128;
    const int tid = threadIdx.x, wid = tid >> 5, lane = tid & 31;
    const int iw  = wid & 3, jw = wid >> 2;       // warp tile: rows iw*32.., cols jw*64..
    const uint32_t sb = smem_u32(smem);

    if (tid == 0) *s_cnt = 0;
    if (tid < 128) s_best[tid] = 0ull;

    // B-tile staging via cp.async: each thread owns 4x16B of the 16KB tile
    const int lr = tid >> 1, lhalf = tid & 1;
    uint32_t bdst[4];
#pragma unroll
    for (int cc = 0; cc < 4; cc++)
        bdst[cc] = swz((uint32_t)(lr * 128 + (lhalf * 4 + cc) * 16));
    const __nv_bfloat16* gB = g_bbf + (size_t)b * TB_ * D_;

    // --- A bf16 tile (group0), B(0) (group1), B(1) (group2) ---
#pragma unroll
    for (int q = 0; q < 4; q++) {
        int fi = tid + q * 256;           // 1024 x 16B
        int r = fi >> 3, ch = fi & 7;
        cp16(sb + SM_A + swz((uint32_t)(r * 128 + ch * 16)),
             g_abf + ((size_t)b * TA_ + i0 + r) * D_ + ch * 8);
    }
    cp_commit();
#pragma unroll
    for (int cc = 0; cc < 4; cc++)
        cp16(sb + SM_B0 + bdst[cc], gB + (size_t)lr * D_ + (lhalf * 4 + cc) * 8);
    cp_commit();
#pragma unroll
    for (int cc = 0; cc < 4; cc++)
        cp16(sb + SM_B1 + bdst[cc], gB + (size_t)(128 + lr) * D_ + (lhalf * 4 + cc) * 8);
    cp_commit();

    const int ar = lane & 15, ac = (lane >> 4) << 3;
    const int bn_l = (lane & 7) + ((lane >> 4) << 3);
    const int bk_l = ((lane >> 3) & 1) << 3;
    const int lr4 = lane >> 2;           // d-fragment row within m16 block

    // --- hoist A fragments: 4 k-steps x 2 m-blocks x 4 regs (loop-invariant) ---
    cp_wait<2>();
    __syncthreads();
    uint32_t afr[4][2][4];
#pragma unroll
    for (int ks = 0; ks < 4; ks++)
#pragma unroll
        for (int m = 0; m < 2; m++)
            ldsm4(afr[ks][m][0], afr[ks][m][1], afr[ks][m][2], afr[ks][m][3],
                  sb + SM_A + swz((uint32_t)((iw * 32 + m * 16 + ar) * 128 + (ks * 16 + ac) * 2)));

    float run[4];                         // per row-slot running max (m0:r, m0:r+8, m1:r, m1:r+8)
#pragma unroll
    for (int s = 0; s < 4; s++) run[s] = NEG_INF;

    for (int jt = 0; jt < 16; jt++) {
        if (jt < 15) cp_wait<1>(); else cp_wait<0>();
        __syncthreads();
        const uint32_t bBase = sb + ((jt & 1) ? SM_B1 : SM_B0);

        float d[2][4][2][4];              // [m][fp][n8][frag]
#pragma unroll
        for (int m = 0; m < 2; m++)
#pragma unroll
            for (int fp = 0; fp < 4; fp++)
#pragma unroll
                for (int n = 0; n < 2; n++)
#pragma unroll
                    for (int k = 0; k < 4; k++) d[m][fp][n][k] = 0.0f;

#pragma unroll
        for (int ks = 0; ks < 4; ks++) {
#pragma unroll
            for (int fp = 0; fp < 4; fp++) {
                uint32_t b0, b1, b2, b3;
                ldsm4(b0, b1, b2, b3,
                      bBase + swz((uint32_t)((jw * 64 + fp * 16 + bn_l) * 128 + (ks * 16 + bk_l) * 2)));
#pragma unroll
                for (int m = 0; m < 2; m++) {
                    mma16816(d[m][fp][0], afr[ks][m][0], afr[ks][m][1], afr[ks][m][2], afr[ks][m][3], b0, b1);
                    mma16816(d[m][fp][1], afr[ks][m][0], afr[ks][m][1], afr[ks][m][2], afr[ks][m][3], b2, b3);
                }
            }
        }

        // per-row-slot tile max over this warp's 64 cols (quad lanes share rows)
        float tm[4];
#pragma unroll
        for (int m = 0; m < 2; m++) {
            float lo = NEG_INF, hi = NEG_INF;
#pragma unroll
            for (int fp = 0; fp < 4; fp++)
#pragma unroll
                for (int n = 0; n < 2; n++) {
                    lo = fmaxf(lo, fmaxf(d[m][fp][n][0], d[m][fp][n][1]));
                    hi = fmaxf(hi, fmaxf(d[m][fp][n][2], d[m][fp][n][3]));
                }
            tm[2 * m] = lo; tm[2 * m + 1] = hi;
        }
#pragma unroll
        for (int s = 0; s < 4; s++) {
            tm[s] = fmaxf(tm[s], __shfl_xor_sync(0xffffffffu, tm[s], 1));
            tm[s] = fmaxf(tm[s], __shfl_xor_sync(0xffffffffu, tm[s], 2));
            run[s] = fmaxf(run[s], tm[s]);
        }
        const float thr0 = run[0] - MARGIN2, thr1 = run[1] - MARGIN2;
        const float thr2 = run[2] - MARGIN2, thr3 = run[3] - MARGIN2;

        // collect superset candidates (local-threshold lower-bounds true row max)
        const int jb0 = jt * 128 + jw * 64 + 2 * (lane & 3);
#pragma unroll
        for (int m = 0; m < 2; m++) {
            const int rA = iw * 32 + m * 16 + lr4;     // rows for frag 0/1
            const float tA = m ? thr2 : thr0;
            const float tB = m ? thr3 : thr1;          // rows +8 for frag 2/3
#pragma unroll
            for (int fp = 0; fp < 4; fp++)
#pragma unroll
                for (int n = 0; n < 2; n++) {
                    int j = jb0 + fp * 16 + n * 8;
                    float* f = d[m][fp][n];
                    if (fmaxf(f[0], f[1]) >= tA) {
                        if (f[0] >= tA) { int s = atomicAdd(s_cnt, 1); if (s < CAND_CAP) s_list[s] = ((uint32_t)rA << 11) | (uint32_t)j; }
                        if (f[1] >= tA) { int s = atomicAdd(s_cnt, 1); if (s < CAND_CAP) s_list[s] = ((uint32_t)rA << 11) | (uint32_t)(j + 1); }
                    }
                    if (fmaxf(f[2], f[3]) >= tB) {
                        if (f[2] >= tB) { int s = atomicAdd(s_cnt, 1); if (s < CAND_CAP) s_list[s] = ((uint32_t)(rA + 8) << 11) | (uint32_t)j; }
                        if (f[3] >= tB) { int s = atomicAdd(s_cnt, 1); if (s < CAND_CAP) s_list[s] = ((uint32_t)(rA + 8) << 11) | (uint32_t)(j + 1); }
                    }
                }
        }

        __syncthreads();
        if (jt + 2 < 16) {
#pragma unroll
            for (int cc = 0; cc < 4; cc++)
                cp16(sb + ((jt & 1) ? SM_B1 : SM_B0) + bdst[cc],
                     gB + (size_t)((jt + 2) * 128 + lr) * D_ + (lhalf * 4 + cc) * 8);
            cp_commit();
        } else if (jt < 15) {
            cp_commit();
        }
    }

    int cnt = *s_cnt; if (cnt > CAND_CAP) cnt = CAND_CAP;

    // exact fp32 rescore: one candidate per thread; packed atomicMax per row
    for (int h = tid; h < cnt; h += 256) {
        uint32_t e = s_list[h];
        int r = (int)(e >> 11), j = (int)(e & 2047u);
        const float4* ar4 = (const float4*)(g_m + ((size_t)b * T_ + 2 * (size_t)(i0 + r)) * D_);
        const float4* br4 = (const float4*)(g_m + ((size_t)b * T_ + 2 * (size_t)j + 1) * D_);
        float acc = 0.0f;
#pragma unroll
        for (int k = 0; k < 16; k++) {
            float4 a4 = ar4[k], b4 = br4[k];
            acc = fmaf(a4.x, b4.x, acc);
            acc = fmaf(a4.y, b4.y, acc);
            acc = fmaf(a4.z, b4.z, acc);
            acc = fmaf(a4.w, b4.w, acc);
        }
        unsigned u = __float_as_uint(acc);
        u = (u & 0x80000000u) ? ~u : (u | 0x80000000u);
        unsigned long long key = ((unsigned long long)u << 32) | (unsigned)(2047 - j);
        atomicMax(&s_best[r], key);
    }
    __syncthreads();

    if (tid < 128) {
        unsigned long long k = s_best[tid];
        unsigned u = (unsigned)(k >> 32);
        float v = __uint_as_float((u & 0x80000000u) ? (u & 0x7fffffffu) : ~u);
        int j = 2047 - (int)(k & 0x7ffu);
        int gi = i0 + tid;
        if (gi == 0) { v = NEG_INF; j = 0; }   // scores[:,0,:] = -inf
        g_nmax[b * TA_ + gi] = v;
        g_nidx[b * TA_ + gi] = j;
    }
}

// ---------------- K3: per-batch selection + CSR build ----------------
__device__ __forceinline__ void bitonic_ull(unsigned long long* a, int n) {
    const int tid = threadIdx.x;
    for (int k = 2; k <= n; k <<= 1) {
        for (int j = k >> 1; j > 0; j >>= 1) {
            __syncthreads();
            for (int i = tid; i < n; i += 1024) {
                int ixj = i ^ j;
                if (ixj > i) {
                    unsigned long long p = a[i], q = a[ixj];
                    bool asc = ((i & k) == 0);
                    if ((p > q) == asc) { a[i] = q; a[ixj] = p; }
                }
            }
        }
    }
    __syncthreads();
}

__global__ __launch_bounds__(1024, 1) void k_select() {
    __shared__ unsigned long long key[2048];
    __shared__ int s_src[1024];
    __shared__ int s_dst[1024];
    const int b = blockIdx.x;
    const int tid = threadIdx.x;

    for (int e = tid; e < 2048; e += 1024) {
        unsigned int u = __float_as_uint(g_nmax[b * TA_ + e]);
        u = (u & 0x80000000u) ? ~u : (u | 0x80000000u);
        key[e] = ((unsigned long long)(~u) << 32) | (unsigned int)e;
    }
    bitonic_ull(key, 2048);

    int src_i = (int)(key[tid] & 0xffffffffu);
    int unm_i = (int)(key[1024 + tid] & 0xffffffffu);
    s_src[tid] = src_i;
    s_dst[tid] = g_nidx[b * TA_ + src_i];
    __syncthreads();

    key[tid] = (unsigned long long)(unsigned int)unm_i;
    bitonic_ull(key, 1024);
    g_unm[b * TUN_ + tid] = (int)(key[tid] & 0xffffffffu);
    __syncthreads();

    key[tid] = ((unsigned long long)(((unsigned)s_dst[tid] << 10) | (unsigned)tid) << 32)
             | (unsigned int)s_src[tid];
    bitonic_ull(key, 1024);

    int d     = (int)((unsigned)(key[tid] >> 32) >> 10);
    int dprev = (tid == 0) ? -1 : (int)((unsigned)(key[tid - 1] >> 32) >> 10);
    for (int j = dprev + 1; j <= d; j++) g_off[b * (TB_ + 1) + j] = tid;
    if (tid == 1023)
        for (int j = d + 1; j <= TB_; j++) g_off[b * (TB_ + 1) + j] = 1024;
    g_csr[b * R_ + tid] = (int)(key[tid] & 0xffffffffu);
}

// ---------------- K4: gather + merge + divide (warp-per-row, 128-thr blocks) ----------------
__global__ __launch_bounds__(128) void k_merge(const float* __restrict__ x,
                                               float* __restrict__ out) {
    int wg   = blockIdx.x * 4 + (threadIdx.x >> 5);
    int b    = wg / TOUT_;
    int r    = wg - b * TOUT_;
    int lane = threadIdx.x & 31;
    const float* xb = x + (size_t)b * T_ * C_;
    float4* orow = (float4*)(out + (size_t)((size_t)b * TOUT_ + r) * C_);

    if (r < TUN_) {
        int src = g_unm[b * TUN_ + r];
        const float4* s4 = (const float4*)(xb + (size_t)(2 * src) * C_);
        float4 v[8];
#pragma unroll
        for (int c = 0; c < 8; c++) v[c] = __ldcs(s4 + lane + 32 * c);
#pragma unroll
        for (int c = 0; c < 8; c++) orow[lane + 32 * c] = v[c];
    } else {
        int j = r - TUN_;
        int s = g_off[b * (TB_ + 1) + j];
        int e = g_off[b * (TB_ + 1) + j + 1];
        const float4* d4 = (const float4*)(xb + (size_t)(2 * j + 1) * C_);
        float4 acc[8];
#pragma unroll
        for (int c = 0; c < 8; c++) acc[c] = __ldcs(d4 + lane + 32 * c);
        for (int p = s; p < e; p++) {
            int src = g_csr[b * R_ + p];
            const float4* s4 = (const float4*)(xb + (size_t)(2 * src) * C_);
#pragma unroll
            for (int c = 0; c < 8; c++) {
                float4 v = __ldcs(s4 + lane + 32 * c);
                acc[c].x += v.x; acc[c].y += v.y; acc[c].z += v.z; acc[c].w += v.w;
            }
        }
        float sz = (float)(1 + e - s);
#pragma unroll
        for (int c = 0; c < 8; c++) {
            acc[c].x = __fdiv_rn(acc[c].x, sz);
            acc[c].y = __fdiv_rn(acc[c].y, sz);
            acc[c].z = __fdiv_rn(acc[c].z, sz);
            acc[c].w = __fdiv_rn(acc[c].w, sz);
            orow[lane + 32 * c] = acc[c];
        }
    }
}

// ---------------- launcher ----------------
extern "C" void kernel_launch(void* const* d_in, const int* in_sizes, int n_in,
                              void* d_out, int out_size) {
    const float* x = nullptr;
    const float* metric = nullptr;
    for (int i = 0; i < n_in; i++) {
        long long sz = in_sizes[i];
        if (sz == (long long)B_ * T_ * C_)      x = (const float*)d_in[i];
        else if (sz == (long long)B_ * T_ * D_) metric = (const float*)d_in[i];
    }
    float* out = (float*)d_out;

    k_normalize<<<(B_ * T_) / 8, 256>>>(metric);

    cudaFuncSetAttribute(k_screen, cudaFuncAttributeMaxDynamicSharedMemorySize, SM_TOT);
    dim3 g2(TA_ / 128, B_);
    k_screen<<<g2, 256, SM_TOT>>>();

    k_select<<<B_, 1024>>>();

    k_merge<<<B_ * TOUT_ / 4, 128>>>(x, out);
}

// round 8
// speedup vs baseline: 1.1601x; 1.1601x over previous
#include <cuda_runtime.h>
#include <cuda_bf16.h>
#include <stdint.h>

#define B_   32
#define T_   4096
#define C_   1024
#define D_   64
#define TA_  2048
#define TB_  2048
#define R_   1024
#define TUN_ 1024
#define TOUT_ 3072

#define NEG_INF __int_as_float(0xff800000)
// |bf16-screened - exact| <= 2^-8 * sum|a_k b_k| + accum <= 0.004 (unit rows). Need 2x.
#define MARGIN2 0.008f
#define CAND_CAP 4096

// ---------------- scratch (static device globals; no runtime alloc) ----------------
__device__ float g_m[(size_t)B_ * T_ * D_];            // normalized metric fp32
__device__ __nv_bfloat16 g_abf[(size_t)B_ * TA_ * D_]; // bf16(normalized) even rows
__device__ __nv_bfloat16 g_bbf[(size_t)B_ * TB_ * D_]; // bf16(normalized) odd rows
__device__ float g_nmax[B_ * TA_];
__device__ int   g_nidx[B_ * TA_];
__device__ int   g_unm [B_ * TUN_];
__device__ int   g_off [B_ * (TB_ + 1)];
__device__ int   g_csr [B_ * R_];

__device__ __forceinline__ uint32_t smem_u32(const void* p) {
    uint32_t a;
    asm("{ .reg .u64 t; cvta.to.shared.u64 t, %1; cvt.u32.u64 %0, t; }" : "=r"(a) : "l"(p));
    return a;
}
__device__ __forceinline__ uint32_t swz(uint32_t x) { return x ^ (((x >> 7) & 7u) << 4); }

__device__ __forceinline__ void cp16(uint32_t dst, const void* src) {
    asm volatile("cp.async.cg.shared.global [%0], [%1], 16;" :: "r"(dst), "l"(src) : "memory");
}
__device__ __forceinline__ void cp_commit() {
    asm volatile("cp.async.commit_group;" ::: "memory");
}
template <int N>
__device__ __forceinline__ void cp_wait() {
    asm volatile("cp.async.wait_group %0;" :: "n"(N) : "memory");
}

__device__ __forceinline__ void ldsm4(uint32_t& r0, uint32_t& r1, uint32_t& r2, uint32_t& r3,
                                      uint32_t addr) {
    asm volatile("ldmatrix.sync.aligned.m8n8.x4.shared.b16 {%0,%1,%2,%3}, [%4];"
                 : "=r"(r0), "=r"(r1), "=r"(r2), "=r"(r3) : "r"(addr));
}
__device__ __forceinline__ void mma16816(float* d, uint32_t a0, uint32_t a1, uint32_t a2,
                                         uint32_t a3, uint32_t b0, uint32_t b1) {
    asm volatile(
        "mma.sync.aligned.m16n8k16.row.col.f32.bf16.bf16.f32 "
        "{%0,%1,%2,%3}, {%4,%5,%6,%7}, {%8,%9}, {%0,%1,%2,%3};"
        : "+f"(d[0]), "+f"(d[1]), "+f"(d[2]), "+f"(d[3])
        : "r"(a0), "r"(a1), "r"(a2), "r"(a3), "r"(b0), "r"(b1));
}

// ---------------- K1: normalize + fp32 copy + bf16 copies (even/odd split) ----------------
__global__ __launch_bounds__(256) void k_normalize(const float* __restrict__ metric) {
    int row  = (blockIdx.x * blockDim.x + threadIdx.x) >> 5;
    int lane = threadIdx.x & 31;
    if (row >= B_ * T_) return;
    float2 v = *(const float2*)(metric + (size_t)row * D_ + 2 * lane);
    float s = v.x * v.x + v.y * v.y;
#pragma unroll
    for (int o = 16; o > 0; o >>= 1) s += __shfl_xor_sync(0xffffffffu, s, o);
    float nrm = __fsqrt_rn(s);
    float x0 = __fdiv_rn(v.x, nrm);
    float x1 = __fdiv_rn(v.y, nrm);
    *(float2*)(g_m + (size_t)row * D_ + 2 * lane) = make_float2(x0, x1);
    int b = row >> 12;
    int t = row & (T_ - 1);
    __nv_bfloat16* arr = (t & 1) ? g_bbf : g_abf;
    size_t off = ((size_t)b * (T_ / 2) + (t >> 1)) * D_ + 2 * lane;
    *(__nv_bfloat162*)(arr + off) =
        __halves2bfloat162(__float2bfloat16_rn(x0), __float2bfloat16_rn(x1));
}

// ---------------- K2: single-pass bf16 HMMA screen + exact fp32 rescore ----------------
// (R6 configuration: warp tile 16i x 128j — measured best at ~160us)
#define SM_A    0
#define SM_B0   16384
#define SM_B1   32768
#define SM_LIST 49152
#define SM_BEST (SM_LIST + CAND_CAP * 4)
#define SM_CNT  (SM_BEST + 128 * 8)
#define SM_TOT  (SM_CNT + 16)

__global__ __launch_bounds__(256, 2) void k_screen() {
    extern __shared__ char smem[];
    uint32_t* s_list = (uint32_t*)(smem + SM_LIST);
    unsigned long long* s_best = (unsigned long long*)(smem + SM_BEST);
    int* s_cnt = (int*)(smem + SM_CNT);

    const int b   = blockIdx.y;
    const int i0  = blockIdx.x * 128;
    const int tid = threadIdx.x, wid = tid >> 5, lane = tid & 31;
    const uint32_t sb = smem_u32(smem);

    if (tid == 0) *s_cnt = 0;
    if (tid < 128) s_best[tid] = 0ull;

    // B-tile staging via cp.async: each thread owns 4x16B of the 16KB tile
    const int lr = tid >> 1, lhalf = tid & 1;
    uint32_t bdst[4];
#pragma unroll
    for (int cc = 0; cc < 4; cc++)
        bdst[cc] = swz((uint32_t)(lr * 128 + (lhalf * 4 + cc) * 16));
    const __nv_bfloat16* gB = g_bbf + (size_t)b * TB_ * D_;

    // --- A bf16 tile via cp.async (group0), B(0) (group1), B(1) (group2) ---
#pragma unroll
    for (int q = 0; q < 4; q++) {
        int fi = tid + q * 256;           // 1024 x 16B
        int r = fi >> 3, ch = fi & 7;
        cp16(sb + SM_A + swz((uint32_t)(r * 128 + ch * 16)),
             g_abf + ((size_t)b * TA_ + i0 + r) * D_ + ch * 8);
    }
    cp_commit();
#pragma unroll
    for (int cc = 0; cc < 4; cc++)
        cp16(sb + SM_B0 + bdst[cc], gB + (size_t)lr * D_ + (lhalf * 4 + cc) * 8);
    cp_commit();
#pragma unroll
    for (int cc = 0; cc < 4; cc++)
        cp16(sb + SM_B1 + bdst[cc], gB + (size_t)(128 + lr) * D_ + (lhalf * 4 + cc) * 8);
    cp_commit();

    const int r0l = wid * 16 + (lane >> 2);   // local row for d[.][0..1]; +8 for d[.][2..3]
    const int ar = lane & 15, ac = (lane >> 4) << 3;
    const int bn_l = (lane & 7) + ((lane >> 4) << 3);
    const int bk_l = ((lane >> 3) & 1) << 3;

    // --- hoist A fragments: 4 k-steps x 4 regs, loop-invariant across j-tiles ---
    cp_wait<2>();          // A tile complete
    __syncthreads();
    uint32_t afr[4][4];
#pragma unroll
    for (int ks = 0; ks < 4; ks++)
        ldsm4(afr[ks][0], afr[ks][1], afr[ks][2], afr[ks][3],
              sb + SM_A + swz((uint32_t)((wid * 16 + ar) * 128 + (ks * 16 + ac) * 2)));

    float run0 = NEG_INF, run1 = NEG_INF;

    for (int jt = 0; jt < 16; jt++) {
        if (jt < 15) cp_wait<1>(); else cp_wait<0>();   // B(jt) complete
        __syncthreads();
        const uint32_t bBase = sb + ((jt & 1) ? SM_B1 : SM_B0);

        float d[16][4];
#pragma unroll
        for (int f = 0; f < 16; f++)
#pragma unroll
            for (int k = 0; k < 4; k++) d[f][k] = 0.0f;

#pragma unroll
        for (int ks = 0; ks < 4; ks++) {
#pragma unroll
            for (int fp = 0; fp < 8; fp++) {
                uint32_t b0, b1, b2, b3;
                ldsm4(b0, b1, b2, b3,
                      bBase + swz((uint32_t)((fp * 16 + bn_l) * 128 + (ks * 16 + bk_l) * 2)));
                mma16816(d[2 * fp],     afr[ks][0], afr[ks][1], afr[ks][2], afr[ks][3], b0, b1);
                mma16816(d[2 * fp + 1], afr[ks][0], afr[ks][1], afr[ks][2], afr[ks][3], b2, b3);
            }
        }

        // per-row tile max (quad lanes share rows), pairwise
        float tm0 = NEG_INF, tm1 = NEG_INF;
#pragma unroll
        for (int f = 0; f < 16; f++) {
            tm0 = fmaxf(tm0, fmaxf(d[f][0], d[f][1]));
            tm1 = fmaxf(tm1, fmaxf(d[f][2], d[f][3]));
        }
        tm0 = fmaxf(tm0, __shfl_xor_sync(0xffffffffu, tm0, 1));
        tm0 = fmaxf(tm0, __shfl_xor_sync(0xffffffffu, tm0, 2));
        tm1 = fmaxf(tm1, __shfl_xor_sync(0xffffffffu, tm1, 1));
        tm1 = fmaxf(tm1, __shfl_xor_sync(0xffffffffu, tm1, 2));
        const float thr0 = fmaxf(run0, tm0) - MARGIN2;
        const float thr1 = fmaxf(run1, tm1) - MARGIN2;
        run0 = fmaxf(run0, tm0);
        run1 = fmaxf(run1, tm1);

        // collect superset candidates: pair pre-filter, rare inner path
        const int jb0 = jt * 128 + 2 * (lane & 3);
#pragma unroll
        for (int f = 0; f < 16; f++) {
            int j = jb0 + f * 8;
            if (fmaxf(d[f][0], d[f][1]) >= thr0) {
                if (d[f][0] >= thr0) { int s = atomicAdd(s_cnt, 1); if (s < CAND_CAP) s_list[s] = ((uint32_t)r0l << 11) | (uint32_t)j; }
                if (d[f][1] >= thr0) { int s = atomicAdd(s_cnt, 1); if (s < CAND_CAP) s_list[s] = ((uint32_t)r0l << 11) | (uint32_t)(j + 1); }
            }
            if (fmaxf(d[f][2], d[f][3]) >= thr1) {
                if (d[f][2] >= thr1) { int s = atomicAdd(s_cnt, 1); if (s < CAND_CAP) s_list[s] = ((uint32_t)(r0l + 8) << 11) | (uint32_t)j; }
                if (d[f][3] >= thr1) { int s = atomicAdd(s_cnt, 1); if (s < CAND_CAP) s_list[s] = ((uint32_t)(r0l + 8) << 11) | (uint32_t)(j + 1); }
            }
        }

        __syncthreads();    // all warps done reading buf[jt&1]
        if (jt + 2 < 16) {  // prefetch B(jt+2) into the buffer just freed
#pragma unroll
            for (int cc = 0; cc < 4; cc++)
                cp16(sb + ((jt & 1) ? SM_B1 : SM_B0) + bdst[cc],
                     gB + (size_t)((jt + 2) * 128 + lr) * D_ + (lhalf * 4 + cc) * 8);
            cp_commit();
        } else if (jt < 15) {
            cp_commit();    // keep group accounting aligned
        }
    }

    int cnt = *s_cnt; if (cnt > CAND_CAP) cnt = CAND_CAP;

    // exact fp32 rescore: one candidate per thread; packed atomicMax per row
    // key = (sortable(value) << 32) | (2047 - j)  -> max key = (value desc, j asc)
    for (int h = tid; h < cnt; h += 256) {
        uint32_t e = s_list[h];
        int r = (int)(e >> 11), j = (int)(e & 2047u);
        const float4* ar4 = (const float4*)(g_m + ((size_t)b * T_ + 2 * (size_t)(i0 + r)) * D_);
        const float4* br4 = (const float4*)(g_m + ((size_t)b * T_ + 2 * (size_t)j + 1) * D_);
        float acc = 0.0f;
#pragma unroll
        for (int k = 0; k < 16; k++) {
            float4 a4 = ar4[k], b4 = br4[k];
            acc = fmaf(a4.x, b4.x, acc);
            acc = fmaf(a4.y, b4.y, acc);
            acc = fmaf(a4.z, b4.z, acc);
            acc = fmaf(a4.w, b4.w, acc);
        }
        unsigned u = __float_as_uint(acc);
        u = (u & 0x80000000u) ? ~u : (u | 0x80000000u);
        unsigned long long key = ((unsigned long long)u << 32) | (unsigned)(2047 - j);
        atomicMax(&s_best[r], key);
    }
    __syncthreads();

    if (tid < 128) {
        unsigned long long k = s_best[tid];
        unsigned u = (unsigned)(k >> 32);
        float v = __uint_as_float((u & 0x80000000u) ? (u & 0x7fffffffu) : ~u);
        int j = 2047 - (int)(k & 0x7ffu);
        int gi = i0 + tid;
        if (gi == 0) { v = NEG_INF; j = 0; }   // scores[:,0,:] = -inf
        g_nmax[b * TA_ + gi] = v;
        g_nidx[b * TA_ + gi] = j;
    }
}

// ---------------- K3: per-batch selection + CSR build ----------------
__device__ __forceinline__ void bitonic_ull(unsigned long long* a, int n) {
    const int tid = threadIdx.x;
    for (int k = 2; k <= n; k <<= 1) {
        for (int j = k >> 1; j > 0; j >>= 1) {
            __syncthreads();
            for (int i = tid; i < n; i += 1024) {
                int ixj = i ^ j;
                if (ixj > i) {
                    unsigned long long p = a[i], q = a[ixj];
                    bool asc = ((i & k) == 0);
                    if ((p > q) == asc) { a[i] = q; a[ixj] = p; }
                }
            }
        }
    }
    __syncthreads();
}

__global__ __launch_bounds__(1024, 1) void k_select() {
    __shared__ unsigned long long key[2048];
    __shared__ int s_src[1024];
    __shared__ int s_dst[1024];
    const int b = blockIdx.x;
    const int tid = threadIdx.x;

    for (int e = tid; e < 2048; e += 1024) {
        unsigned int u = __float_as_uint(g_nmax[b * TA_ + e]);
        u = (u & 0x80000000u) ? ~u : (u | 0x80000000u);
        key[e] = ((unsigned long long)(~u) << 32) | (unsigned int)e;
    }
    bitonic_ull(key, 2048);

    int src_i = (int)(key[tid] & 0xffffffffu);
    int unm_i = (int)(key[1024 + tid] & 0xffffffffu);
    s_src[tid] = src_i;
    s_dst[tid] = g_nidx[b * TA_ + src_i];
    __syncthreads();

    key[tid] = (unsigned long long)(unsigned int)unm_i;
    bitonic_ull(key, 1024);
    g_unm[b * TUN_ + tid] = (int)(key[tid] & 0xffffffffu);
    __syncthreads();

    key[tid] = ((unsigned long long)(((unsigned)s_dst[tid] << 10) | (unsigned)tid) << 32)
             | (unsigned int)s_src[tid];
    bitonic_ull(key, 1024);

    int d     = (int)((unsigned)(key[tid] >> 32) >> 10);
    int dprev = (tid == 0) ? -1 : (int)((unsigned)(key[tid - 1] >> 32) >> 10);
    for (int j = dprev + 1; j <= d; j++) g_off[b * (TB_ + 1) + j] = tid;
    if (tid == 1023)
        for (int j = d + 1; j <= TB_; j++) g_off[b * (TB_ + 1) + j] = 1024;
    g_csr[b * R_ + tid] = (int)(key[tid] & 0xffffffffu);
}

// ---------------- K4: gather + merge + divide (warp-per-row, 128-thr blocks) ----------------
__global__ __launch_bounds__(128) void k_merge(const float* __restrict__ x,
                                               float* __restrict__ out) {
    int wg   = blockIdx.x * 4 + (threadIdx.x >> 5);
    int b    = wg / TOUT_;
    int r    = wg - b * TOUT_;
    int lane = threadIdx.x & 31;
    const float* xb = x + (size_t)b * T_ * C_;
    float4* orow = (float4*)(out + (size_t)((size_t)b * TOUT_ + r) * C_);

    if (r < TUN_) {
        int src = g_unm[b * TUN_ + r];
        const float4* s4 = (const float4*)(xb + (size_t)(2 * src) * C_);
        float4 v[8];
#pragma unroll
        for (int c = 0; c < 8; c++) v[c] = __ldcs(s4 + lane + 32 * c);
#pragma unroll
        for (int c = 0; c < 8; c++) orow[lane + 32 * c] = v[c];
    } else {
        int j = r - TUN_;
        int s = g_off[b * (TB_ + 1) + j];
        int e = g_off[b * (TB_ + 1) + j + 1];
        const float4* d4 = (const float4*)(xb + (size_t)(2 * j + 1) * C_);
        float4 acc[8];
#pragma unroll
        for (int c = 0; c < 8; c++) acc[c] = __ldcs(d4 + lane + 32 * c);
        for (int p = s; p < e; p++) {
            int src = g_csr[b * R_ + p];
            const float4* s4 = (const float4*)(xb + (size_t)(2 * src) * C_);
#pragma unroll
            for (int c = 0; c < 8; c++) {
                float4 v = __ldcs(s4 + lane + 32 * c);
                acc[c].x += v.x; acc[c].y += v.y; acc[c].z += v.z; acc[c].w += v.w;
            }
        }
        float sz = (float)(1 + e - s);
#pragma unroll
        for (int c = 0; c < 8; c++) {
            acc[c].x = __fdiv_rn(acc[c].x, sz);
            acc[c].y = __fdiv_rn(acc[c].y, sz);
            acc[c].z = __fdiv_rn(acc[c].z, sz);
            acc[c].w = __fdiv_rn(acc[c].w, sz);
            orow[lane + 32 * c] = acc[c];
        }
    }
}

// ---------------- launcher ----------------
extern "C" void kernel_launch(void* const* d_in, const int* in_sizes, int n_in,
                              void* d_out, int out_size) {
    const float* x = nullptr;
    const float* metric = nullptr;
    for (int i = 0; i < n_in; i++) {
        long long sz = in_sizes[i];
        if (sz == (long long)B_ * T_ * C_)      x = (const float*)d_in[i];
        else if (sz == (long long)B_ * T_ * D_) metric = (const float*)d_in[i];
    }
    float* out = (float*)d_out;

    k_normalize<<<(B_ * T_) / 8, 256>>>(metric);

    cudaFuncSetAttribute(k_screen, cudaFuncAttributeMaxDynamicSharedMemorySize, SM_TOT);
    dim3 g2(TA_ / 128, B_);
    k_screen<<<g2, 256, SM_TOT>>>();

    k_select<<<B_, 1024>>>();

    k_merge<<<B_ * TOUT_ / 4, 128>>>(x, out);
}